// round 5
// baseline (speedup 1.0000x reference)
#include <cuda_runtime.h>
#include <cuda_bf16.h>

// GNNIntraAgg: out[b, :] = relu( (1/K) * sum_k features[neigh_ids[b,k], :] )
// B=16384, K=32, N=100000, D=256 (fp32).
//
// R5: fully warp-independent version.
//  - No smem / __syncthreads: each warp loads its 32 neighbor ids with one
//    coalesced lane load and broadcasts via __shfl_sync.
//  - Persistent grid-stride: grid = 148 SMs x 5 resident CTAs; each warp
//    processes ~2.8 output rows -> no wave-transition / CTA-setup overhead.
//  - LDG.256 + L2::evict_last gathers (keep the 102MB table L2-resident),
//    4-deep load batches for MLP, streaming output stores.

#define K_NEIGH 32
#define WARPS_PER_BLOCK 8
#define THREADS (WARPS_PER_BLOCK * 32)   // 256
#define LBATCH 4
#define NUM_SMS 148
#define BLOCKS_PER_SM 5

__device__ __forceinline__ void ldg256_evict_last(const float* p, float4& a, float4& b)
{
    asm volatile("ld.global.nc.L2::evict_last.v8.b32 "
                 "{%0,%1,%2,%3,%4,%5,%6,%7}, [%8];"
                 : "=f"(a.x), "=f"(a.y), "=f"(a.z), "=f"(a.w),
                   "=f"(b.x), "=f"(b.y), "=f"(b.z), "=f"(b.w)
                 : "l"(p));
}

__global__ __launch_bounds__(THREADS)
void gnn_agg_kernel(const int* __restrict__ neigh_ids,
                    const float* __restrict__ feat,
                    float4* __restrict__ out,
                    int B)
{
    const int lane        = threadIdx.x & 31;
    const int warp_global = (blockIdx.x * WARPS_PER_BLOCK) + (threadIdx.x >> 5);
    const int warp_count  = gridDim.x * WARPS_PER_BLOCK;

    for (int row = warp_global; row < B; row += warp_count) {
        // One coalesced load: lane k holds neigh_ids[row][k].
        const int my_id = neigh_ids[row * K_NEIGH + lane];

        float acc[8];
#pragma unroll
        for (int i = 0; i < 8; ++i) acc[i] = 0.f;

#pragma unroll
        for (int kb = 0; kb < K_NEIGH; kb += LBATCH) {
            float4 va[LBATCH], vb[LBATCH];
#pragma unroll
            for (int j = 0; j < LBATCH; ++j) {
                const int id = __shfl_sync(0xFFFFFFFFu, my_id, kb + j);
                const float* p = feat + (long)id * 256 + lane * 8;
                ldg256_evict_last(p, va[j], vb[j]);
            }
#pragma unroll
            for (int j = 0; j < LBATCH; ++j) {
                acc[0] += va[j].x;  acc[1] += va[j].y;
                acc[2] += va[j].z;  acc[3] += va[j].w;
                acc[4] += vb[j].x;  acc[5] += vb[j].y;
                acc[6] += vb[j].z;  acc[7] += vb[j].w;
            }
        }

        const float inv = 1.0f / (float)K_NEIGH;
        float4 o0, o1;
        o0.x = fmaxf(acc[0] * inv, 0.f);  o0.y = fmaxf(acc[1] * inv, 0.f);
        o0.z = fmaxf(acc[2] * inv, 0.f);  o0.w = fmaxf(acc[3] * inv, 0.f);
        o1.x = fmaxf(acc[4] * inv, 0.f);  o1.y = fmaxf(acc[5] * inv, 0.f);
        o1.z = fmaxf(acc[6] * inv, 0.f);  o1.w = fmaxf(acc[7] * inv, 0.f);

        // Streaming stores: don't evict the feature table from L2.
        float4* orow = out + (long)row * 64 + lane * 2;
        __stcs(orow,     o0);
        __stcs(orow + 1, o1);
    }
}

extern "C" void kernel_launch(void* const* d_in, const int* in_sizes, int n_in,
                              void* d_out, int out_size)
{
    const int* neigh_ids = (const int*)d_in[0];     // [B, K] int32
    const float* feat    = (const float*)d_in[1];   // [N, D] fp32
    float4* out          = (float4*)d_out;          // [B, D] fp32

    const int B = in_sizes[0] / K_NEIGH;            // 16384
    const int grid = NUM_SMS * BLOCKS_PER_SM;       // 740 persistent blocks

    gnn_agg_kernel<<<grid, THREADS>>>(neigh_ids, feat, out, B);
}

// round 6
// speedup vs baseline: 1.1096x; 1.1096x over previous
#include <cuda_runtime.h>
#include <cuda_bf16.h>

// GNNIntraAgg: out[b, :] = relu( (1/K) * sum_k features[neigh_ids[b,k], :] )
// B=16384, K=32, N=100000, D=256 (fp32).
//
// R6: R4 compute structure (smem-broadcast ids, warp-per-row, LDG.256
// evict_last gathers, 4-deep batches) made persistent:
//  - grid = 740 = 148 SMs x 5 resident CTAs (regs=44) -> single wave.
//  - Each block loops over row-tiles (8 rows each); the NEXT tile's 256 ids
//    are loaded before the current tile's gathers (overlap) and stored to a
//    double-buffered smem array after. One __syncthreads per tile.

#define K_NEIGH 32
#define WARPS_PER_BLOCK 8
#define THREADS (WARPS_PER_BLOCK * 32)   // 256
#define LBATCH 4
#define GRID 740                          // 148 SMs * 5 CTAs/SM

__device__ __forceinline__ void ldg256_evict_last(const float* p, float4& a, float4& b)
{
    asm volatile("ld.global.nc.L2::evict_last.v8.b32 "
                 "{%0,%1,%2,%3,%4,%5,%6,%7}, [%8];"
                 : "=f"(a.x), "=f"(a.y), "=f"(a.z), "=f"(a.w),
                   "=f"(b.x), "=f"(b.y), "=f"(b.z), "=f"(b.w)
                 : "l"(p));
}

__global__ __launch_bounds__(THREADS)
void gnn_agg_kernel(const int* __restrict__ neigh_ids,
                    const float* __restrict__ feat,
                    float4* __restrict__ out,
                    int ntiles)
{
    __shared__ int s_ids[2][THREADS];    // [buf][row_in_tile*32 + k]

    const int tid  = threadIdx.x;
    const int w    = tid >> 5;           // warp = row within tile
    const int lane = tid & 31;           // lane = 32B chunk of the feature row

    int tile = blockIdx.x;
    if (tile >= ntiles) return;

    // Prologue: stage tile 0's ids (256 ints, one per thread).
    s_ids[0][tid] = neigh_ids[tile * THREADS + tid];
    __syncthreads();

    int buf = 0;
    for (; tile < ntiles; tile += GRID) {
        const int next = tile + GRID;
        int next_id = 0;
        if (next < ntiles)                       // issue early: overlaps gathers
            next_id = neigh_ids[next * THREADS + tid];

        const int* ids = &s_ids[buf][w * K_NEIGH];

        float acc[8];
#pragma unroll
        for (int i = 0; i < 8; ++i) acc[i] = 0.f;

#pragma unroll
        for (int kb = 0; kb < K_NEIGH; kb += LBATCH) {
            float4 va[LBATCH], vb[LBATCH];
#pragma unroll
            for (int j = 0; j < LBATCH; ++j) {
                const int id = ids[kb + j];      // warp-broadcast smem read
                const float* p = feat + (long)id * 256 + lane * 8;
                ldg256_evict_last(p, va[j], vb[j]);
            }
#pragma unroll
            for (int j = 0; j < LBATCH; ++j) {
                acc[0] += va[j].x;  acc[1] += va[j].y;
                acc[2] += va[j].z;  acc[3] += va[j].w;
                acc[4] += vb[j].x;  acc[5] += vb[j].y;
                acc[6] += vb[j].z;  acc[7] += vb[j].w;
            }
        }

        const float inv = 1.0f / (float)K_NEIGH;
        float4 o0, o1;
        o0.x = fmaxf(acc[0] * inv, 0.f);  o0.y = fmaxf(acc[1] * inv, 0.f);
        o0.z = fmaxf(acc[2] * inv, 0.f);  o0.w = fmaxf(acc[3] * inv, 0.f);
        o1.x = fmaxf(acc[4] * inv, 0.f);  o1.y = fmaxf(acc[5] * inv, 0.f);
        o1.z = fmaxf(acc[6] * inv, 0.f);  o1.w = fmaxf(acc[7] * inv, 0.f);

        // Streaming stores: don't evict the feature table from L2.
        float4* orow = out + (long)(tile * WARPS_PER_BLOCK + w) * 64 + lane * 2;
        __stcs(orow,     o0);
        __stcs(orow + 1, o1);

        // Commit prefetched ids to the other buffer, then flip.
        if (next < ntiles)
            s_ids[buf ^ 1][tid] = next_id;
        __syncthreads();
        buf ^= 1;
    }
}

extern "C" void kernel_launch(void* const* d_in, const int* in_sizes, int n_in,
                              void* d_out, int out_size)
{
    const int* neigh_ids = (const int*)d_in[0];     // [B, K] int32
    const float* feat    = (const float*)d_in[1];   // [N, D] fp32
    float4* out          = (float4*)d_out;          // [B, D] fp32

    const int B = in_sizes[0] / K_NEIGH;            // 16384
    const int ntiles = B / WARPS_PER_BLOCK;         // 2048 row-tiles

    gnn_agg_kernel<<<GRID, THREADS>>>(neigh_ids, feat, out, ntiles);
}